// round 2
// baseline (speedup 1.0000x reference)
#include <cuda_runtime.h>

#define NB 8
#define NT 64
#define NA 100000
#define NF 84

// scratch (device globals — no allocation allowed)
__device__ unsigned long long g_best[NB * NT];
__device__ int g_tfa[NB * NA];

__global__ void init_kernel() {
    int i = threadIdx.x;
    if (i < NB * NT) g_best[i] = 0ull;
}

__global__ void __launch_bounds__(256) main_kernel(
    const float* __restrict__ labels,
    const float* __restrict__ anchors,
    float* __restrict__ out_fore,
    float* __restrict__ out_back)
{
    __shared__ float sbx1[NT], sby1[NT], sbx2[NT], sby2[NT], sarea[NT];
    __shared__ unsigned long long sbest[NT];

    const int b = blockIdx.y;
    const int tid = threadIdx.x;

    if (tid < NT) {
        const float* lb = labels + ((size_t)b * NT + tid) * NF;
        float cx = lb[0], cy = lb[1], w = lb[2], h = lb[3];
        float hw = __fmul_rn(w, 0.5f);
        float hh = __fmul_rn(h, 0.5f);
        float x1 = __fsub_rn(cx, hw);
        float y1 = __fsub_rn(cy, hh);
        float x2 = __fadd_rn(cx, hw);
        float y2 = __fadd_rn(cy, hh);
        sbx1[tid] = x1; sby1[tid] = y1; sbx2[tid] = x2; sby2[tid] = y2;
        sarea[tid] = __fmul_rn(__fsub_rn(x2, x1), __fsub_rn(y2, y1));
        sbest[tid] = 0ull;
    }
    __syncthreads();

    const int a = blockIdx.x * blockDim.x + tid;
    const bool active = (a < NA);

    float ax1 = 0.f, ay1 = 0.f, ax2 = 0.f, ay2 = 0.f, aarea = 0.f;
    if (active) {
        float4 av = __ldg(((const float4*)anchors) + a);
        float hw = __fmul_rn(av.z, 0.5f);
        float hh = __fmul_rn(av.w, 0.5f);
        ax1 = __fsub_rn(av.x, hw);
        ay1 = __fsub_rn(av.y, hh);
        ax2 = __fadd_rn(av.x, hw);
        ay2 = __fadd_rn(av.y, hh);
        aarea = __fmul_rn(__fsub_rn(ax2, ax1), __fsub_rn(ay2, ay1));
    }

    const unsigned int lokey = 0xFFFFFFFFu - (unsigned int)a; // smaller idx -> bigger key
    float best_q = -1.0f;
    int best_t = 0;

#pragma unroll 4
    for (int t = 0; t < NT; t++) {
        float ltx = fmaxf(ax1, sbx1[t]);
        float lty = fmaxf(ay1, sby1[t]);
        float rbx = fminf(ax2, sbx2[t]);
        float rby = fminf(ay2, sby2[t]);
        float ww = fmaxf(__fsub_rn(rbx, ltx), 0.0f);
        float hh = fmaxf(__fsub_rn(rby, lty), 0.0f);
        float inter = __fmul_rn(ww, hh);
        // reference: inter / (((area_a + area_b) - inter) + 1e-9)
        float denom = __fadd_rn(__fsub_rn(__fadd_rn(aarea, sarea[t]), inter), 1e-9f);
        float q = __fdiv_rn(inter, denom);

        if (active) {
            if (q > best_q) { best_q = q; best_t = t; }  // strict > => first index on ties
            unsigned long long key =
                ((unsigned long long)__float_as_uint(q) << 32) | (unsigned long long)lokey;
            if (key > sbest[t]) atomicMax(&sbest[t], key);  // read-filter cuts atomics ~40x
        }
    }

    if (active) {
        bool fore = (best_q >= 0.5f);
        bool back = (!fore) && (best_q < 0.4f);
        size_t o = (size_t)b * NA + a;
        out_fore[o] = fore ? 1.0f : 0.0f;
        out_back[o] = back ? 1.0f : 0.0f;
        g_tfa[o] = best_t;
    }

    __syncthreads();
    if (tid < NT) atomicMax(&g_best[b * NT + tid], sbest[tid]);
}

// MAX_FOR_TARGET: the winning anchor per (b, t) is always foreground, never background.
__global__ void winner_kernel(float* __restrict__ out_fore, float* __restrict__ out_back) {
    int i = threadIdx.x;
    if (i >= NB * NT) return;
    unsigned long long key = g_best[i];
    int b = i / NT;
    unsigned int a = 0xFFFFFFFFu - (unsigned int)(key & 0xFFFFFFFFull);
    size_t o = (size_t)b * NA + (size_t)a;
    out_fore[o] = 1.0f;
    out_back[o] = 0.0f;
}

// assigned_target[b, a, :] = labels[b, tfa[b,a], :]  (84 f32 = 21 float4 per anchor)
__global__ void __launch_bounds__(256) gather_kernel(
    const float* __restrict__ labels, float* __restrict__ out_at)
{
    long long gid = (long long)blockIdx.x * blockDim.x + threadIdx.x;
    const long long total = (long long)NB * NA * 21;
    if (gid >= total) return;
    int q = (int)(gid % 21);
    int aidx = (int)(gid / 21);
    int b = aidx / NA;
    int t = __ldg(&g_tfa[aidx]);
    const float4* src = (const float4*)(labels + ((size_t)(b * NT + t)) * NF);  // 336B-aligned
    float4 v = src[q];
    float4* dst = (float4*)(out_at + (size_t)aidx * NF);
    dst[q] = v;
}

extern "C" void kernel_launch(void* const* d_in, const int* in_sizes, int n_in,
                              void* d_out, int out_size)
{
    const float* labels;
    const float* anchors;
    // labels = 8*64*84 = 43008 elems, anchors = 1*100000*4 = 400000 elems
    if (in_sizes[0] == NB * NT * NF) {
        labels  = (const float*)d_in[0];
        anchors = (const float*)d_in[1];
    } else {
        labels  = (const float*)d_in[1];
        anchors = (const float*)d_in[0];
    }

    float* out      = (float*)d_out;
    float* out_fore = out;
    float* out_back = out + (size_t)NB * NA;
    float* out_at   = out + (size_t)2 * NB * NA;

    init_kernel<<<1, NB * NT>>>();

    dim3 grid((NA + 255) / 256, NB);
    main_kernel<<<grid, 256>>>(labels, anchors, out_fore, out_back);

    winner_kernel<<<1, NB * NT>>>(out_fore, out_back);

    const long long total = (long long)NB * NA * 21;  // 16.8M threads
    gather_kernel<<<(unsigned)((total + 255) / 256), 256>>>(labels, out_at);
}

// round 3
// speedup vs baseline: 1.2185x; 1.2185x over previous
#include <cuda_runtime.h>

#define NB 8
#define NT 64
#define NA 100000
#define NF 84
#define BLK 256
#define APT 2
#define APB (BLK * APT)   // anchors per block = 512

// scratch (device globals — no allocation allowed)
__device__ unsigned long long g_best[NB * NT];

__global__ void init_kernel() {
    int i = threadIdx.x;
    if (i < NB * NT) g_best[i] = 0ull;
}

__global__ void __launch_bounds__(256) fused_kernel(
    const float* __restrict__ labels,
    const float* __restrict__ anchors,
    float* __restrict__ out_fore,
    float* __restrict__ out_back,
    float* __restrict__ out_at)
{
    __shared__ float sbx1[NT], sby1[NT], sbx2[NT], sby2[NT], sarea[NT];
    __shared__ unsigned long long sbest[NT];
    __shared__ int s_bt[APB];

    const int b = blockIdx.y;
    const int tid = threadIdx.x;

    if (tid < NT) {
        const float* lb = labels + ((size_t)b * NT + tid) * NF;
        float cx = lb[0], cy = lb[1], w = lb[2], h = lb[3];
        float hw = __fmul_rn(w, 0.5f);
        float hh = __fmul_rn(h, 0.5f);
        float x1 = __fsub_rn(cx, hw);
        float y1 = __fsub_rn(cy, hh);
        float x2 = __fadd_rn(cx, hw);
        float y2 = __fadd_rn(cy, hh);
        sbx1[tid] = x1; sby1[tid] = y1; sbx2[tid] = x2; sby2[tid] = y2;
        sarea[tid] = __fmul_rn(__fsub_rn(x2, x1), __fsub_rn(y2, y1));
        sbest[tid] = 0ull;
    }
    __syncthreads();

    const int base_a = blockIdx.x * APB;

    int   aidx[APT];
    bool  act[APT];
    float ax1[APT], ay1[APT], ax2[APT], ay2[APT], aarea[APT];
    unsigned int lokey[APT];
    float best_q[APT];
    int   best_t[APT];

#pragma unroll
    for (int j = 0; j < APT; j++) {
        int a = base_a + j * BLK + tid;
        aidx[j] = a;
        act[j] = (a < NA);
        lokey[j] = 0xFFFFFFFFu - (unsigned int)a;   // smaller idx -> bigger key
        best_q[j] = -1.0f;
        best_t[j] = 0;
        ax1[j] = ay1[j] = ax2[j] = ay2[j] = aarea[j] = 0.f;
        if (act[j]) {
            float4 av = __ldg(((const float4*)anchors) + a);
            float hw = __fmul_rn(av.z, 0.5f);
            float hh = __fmul_rn(av.w, 0.5f);
            ax1[j] = __fsub_rn(av.x, hw);
            ay1[j] = __fsub_rn(av.y, hh);
            ax2[j] = __fadd_rn(av.x, hw);
            ay2[j] = __fadd_rn(av.y, hh);
            aarea[j] = __fmul_rn(__fsub_rn(ax2[j], ax1[j]), __fsub_rn(ay2[j], ay1[j]));
        }
    }

#pragma unroll 4
    for (int t = 0; t < NT; t++) {
        float bx1 = sbx1[t], by1 = sby1[t], bx2 = sbx2[t], by2 = sby2[t], ba = sarea[t];
        unsigned long long kmax = 0ull;

#pragma unroll
        for (int j = 0; j < APT; j++) {
            float ltx = fmaxf(ax1[j], bx1);
            float lty = fmaxf(ay1[j], by1);
            float rbx = fminf(ax2[j], bx2);
            float rby = fminf(ay2[j], by2);
            float ww = fmaxf(__fsub_rn(rbx, ltx), 0.0f);
            float hh = fmaxf(__fsub_rn(rby, lty), 0.0f);
            float inter = __fmul_rn(ww, hh);
            // reference: inter / (((area_a + area_b) - inter) + 1e-9)
            float denom = __fadd_rn(__fsub_rn(__fadd_rn(aarea[j], ba), inter), 1e-9f);
            float q = __fdiv_rn(inter, denom);

            if (act[j]) {
                if (q > best_q[j]) { best_q[j] = q; best_t[j] = t; } // strict > => first idx on tie
                unsigned long long key =
                    ((unsigned long long)__float_as_uint(q) << 32) | (unsigned long long)lokey[j];
                if (key > kmax) kmax = key;
            }
        }

        if (kmax > sbest[t]) atomicMax(&sbest[t], kmax);  // read-filter cuts atomics
    }

#pragma unroll
    for (int j = 0; j < APT; j++) {
        s_bt[j * BLK + tid] = best_t[j];
        if (act[j]) {
            bool fore = (best_q[j] >= 0.5f);
            bool back = (!fore) && (best_q[j] < 0.4f);
            size_t o = (size_t)b * NA + aidx[j];
            out_fore[o] = fore ? 1.0f : 0.0f;
            out_back[o] = back ? 1.0f : 0.0f;
        }
    }

    __syncthreads();
    if (tid < NT) atomicMax(&g_best[b * NT + tid], sbest[tid]);

    // fused gather: assigned_target[b, a, :] = labels[b, best_t[a], :]
    // (84 f32 = 21 float4 per anchor; labels rows are 336B = 16B-aligned)
    const float4* lbase = (const float4*)(labels + (size_t)b * NT * NF);  // row t at offset t*21
    float* obase = out_at + ((size_t)b * NA + base_a) * NF;
#pragma unroll 2
    for (int idx = tid; idx < APB * 21; idx += BLK) {
        int al = idx / 21;
        int q  = idx - al * 21;
        if (base_a + al < NA) {
            int t = s_bt[al];
            float4 v = __ldg(lbase + t * 21 + q);
            __stcs((float4*)(obase + (size_t)al * NF) + q, v);
        }
    }
}

// MAX_FOR_TARGET: the winning anchor per (b, t) is always foreground, never background.
__global__ void winner_kernel(float* __restrict__ out_fore, float* __restrict__ out_back) {
    int i = threadIdx.x;
    if (i >= NB * NT) return;
    unsigned long long key = g_best[i];
    int b = i / NT;
    unsigned int a = 0xFFFFFFFFu - (unsigned int)(key & 0xFFFFFFFFull);
    size_t o = (size_t)b * NA + (size_t)a;
    out_fore[o] = 1.0f;
    out_back[o] = 0.0f;
}

extern "C" void kernel_launch(void* const* d_in, const int* in_sizes, int n_in,
                              void* d_out, int out_size)
{
    const float* labels;
    const float* anchors;
    // labels = 8*64*84 = 43008 elems, anchors = 1*100000*4 = 400000 elems
    if (in_sizes[0] == NB * NT * NF) {
        labels  = (const float*)d_in[0];
        anchors = (const float*)d_in[1];
    } else {
        labels  = (const float*)d_in[1];
        anchors = (const float*)d_in[0];
    }

    float* out      = (float*)d_out;
    float* out_fore = out;
    float* out_back = out + (size_t)NB * NA;
    float* out_at   = out + (size_t)2 * NB * NA;

    init_kernel<<<1, NB * NT>>>();

    dim3 grid((NA + APB - 1) / APB, NB);
    fused_kernel<<<grid, BLK>>>(labels, anchors, out_fore, out_back, out_at);

    winner_kernel<<<1, NB * NT>>>(out_fore, out_back);
}